// round 13
// baseline (speedup 1.0000x reference)
#include <cuda_runtime.h>
#include <cuda_bf16.h>

#define BATCH   8
#define NPTS    16384
#define BN      (BATCH * NPTS)
#define TILE    128
#define NTILES  (BN / TILE)        // 1024
#define THREADS 256                // 8 warps: 2 m-groups(64 rows) x 4 n-groups

// ---------------- mid/final smem layout (bf16 units) ----------------
#define MF_P_H  0                  // 128x136
#define MF_P_L  17408
#define MF_Q_H  34816              // 128x136
#define MF_Q_L  52224
#define MF_WS   69632              // weight ring 16384 elems (32KB)
#define MF_END  86016
#define MF_M_H  0                  // conv1 out 128x72, overlays P
#define MF_M_L  9216
#define SMEM_MF (MF_END*2 + 1088)  // 173120 B -> 1 CTA/SM

// ---------------- k0 smem layout ----------------
#define K0_X_H  0                  // 128x40
#define K0_X_L  5120
#define K0_C_H  10240              // 128x136 (half of mlp_in out; reused)
#define K0_C_L  27648
#define K0_M_H  45056              // 128x72 (conv1 out)
#define K0_M_L  54272
#define K0_IO_H 10240              // conv2 out overlays C
#define K0_IO_L 27648
#define K0_WS   63488              // 16384-elem ring
#define K0_END  79872
#define SMEM_K0 (K0_END*2 + 1088)  // 160832 B -> 1 CTA/SM

#define LD_136 136
#define LD_72  72
#define LD_40  40

// ---------------- global scratch ----------------
__device__ unsigned g_featA[BN * 128];
__device__ unsigned g_featB[BN * 128];
__device__ float    g_pool[3 * BATCH * 64 * 128];
__device__ float    g_p2l[8 * 64 * 128];
__device__ __nv_bfloat16 g_wh[180224];
__device__ __nv_bfloat16 g_wl[180224];

#define OFF_WIN 0        // 256 x 32
#define OFF_W1  8192     // 3 x (64 x 256)
#define OFF_W2  57344    // 3 x (128 x 64)
#define OFF_W3  81920    // 3 x (128 x 128)
#define OFF_WO1 131072   // 128 x 256
#define OFF_WO2 163840   // 128 x 128

__global__ void init_kernel(float* __restrict__ out) {
    int i = blockIdx.x * blockDim.x + threadIdx.x;
    if (i < 3 * BATCH * 64 * 128) g_pool[i] = 0.0f;
    if (i < BATCH * 128) out[i] = 0.0f;
}

__global__ void warm_kernel() {}

__global__ void convert_all(const float* __restrict__ w_in, const float* __restrict__ w1,
                            const float* __restrict__ w2, const float* __restrict__ w3,
                            const float* __restrict__ wo1, const float* __restrict__ wo2) {
    int i = blockIdx.x * blockDim.x + threadIdx.x;
    if (i >= 180224) return;
    const float* src; int base, cin, kpad;
    if (i < 8192)        { src = w_in; base = 0;      cin = 28;  kpad = 32;  }
    else if (i < 57344)  { src = w1;   base = 8192;   cin = 256; kpad = 256; }
    else if (i < 81920)  { src = w2;   base = 57344;  cin = 64;  kpad = 64;  }
    else if (i < 131072) { src = w3;   base = 81920;  cin = 128; kpad = 128; }
    else if (i < 163840) { src = wo1;  base = 131072; cin = 256; kpad = 256; }
    else                 { src = wo2;  base = 163840; cin = 128; kpad = 128; }
    int j = i - base, r = j / kpad, k = j - r * kpad;
    float v = (k < cin) ? src[r * cin + k] : 0.0f;
    __nv_bfloat16 h = __float2bfloat16(v);
    g_wh[i] = h;
    g_wl[i] = __float2bfloat16(v - __bfloat162float(h));
}

// p2l[b][cl][j] = bias[j] + W[j][128..255] . pool[b][cl][:]
__global__ void p2l_kernel(const float* __restrict__ w, const float* __restrict__ bias,
                           const float* __restrict__ pool, float* __restrict__ dst,
                           int ncl, int J) {
    __shared__ float sp[128];
    int bc = blockIdx.x;
    int b = bc / ncl, cl = bc - b * ncl;
    sp[threadIdx.x] = pool[b * 8192 + cl * 128 + threadIdx.x];
    __syncthreads();
    for (int j = threadIdx.x; j < J; j += 128) {
        const float4* wr = (const float4*)(w + j * 256 + 128);
        float s = bias[j];
#pragma unroll
        for (int k = 0; k < 32; k++) {
            float4 wv = wr[k];
            float4 pv = ((const float4*)sp)[k];
            s += wv.x * pv.x + wv.y * pv.y + wv.z * pv.z + wv.w * pv.w;
        }
        dst[bc * J + j] = s;
    }
}

// ---------------- helpers ----------------
__device__ __forceinline__ void mma_bf16(float c[4], const unsigned a[4],
                                         unsigned b0, unsigned b1) {
    asm volatile(
        "mma.sync.aligned.m16n8k16.row.col.f32.bf16.bf16.f32 "
        "{%0,%1,%2,%3}, {%4,%5,%6,%7}, {%8,%9}, {%0,%1,%2,%3};"
        : "+f"(c[0]), "+f"(c[1]), "+f"(c[2]), "+f"(c[3])
        : "r"(a[0]), "r"(a[1]), "r"(a[2]), "r"(a[3]), "r"(b0), "r"(b1));
}
__device__ __forceinline__ unsigned sptr(const void* p) {
    return (unsigned)__cvta_generic_to_shared(p);
}
__device__ __forceinline__ void ldsm4(unsigned r[4], const void* p) {
    asm volatile("ldmatrix.sync.aligned.m8n8.x4.shared.b16 {%0,%1,%2,%3}, [%4];"
                 : "=r"(r[0]), "=r"(r[1]), "=r"(r[2]), "=r"(r[3]) : "r"(sptr(p)));
}
__device__ __forceinline__ unsigned pack2(__nv_bfloat16 x, __nv_bfloat16 y) {
    return ((unsigned)__bfloat16_as_ushort(y) << 16) | (unsigned)__bfloat16_as_ushort(x);
}
#define CP16(d, s) asm volatile("cp.async.cg.shared.global [%0], [%1], 16;" :: "r"(d), "l"(s))

// ================= GEMM mainloop: MT m-tiles x NT n-tiles per warp =================
// 8 warps: 2 m-groups (MT*16 rows each) x 4 n-groups. Weight chunk: [COUT x 32] bf16,
// 64B rows, XOR swizzle seg^=(row>>1)&3. KC=32 double-buffered ring; one drain/layer.
template<int MT, int NT, int KW, int WSTR>
__device__ __forceinline__ void gemm_core(float (*acc)[NT][4], __nv_bfloat16* sm,
                                          int aH, int aL, int ldA,
                                          const __nv_bfloat16* __restrict__ gWh,
                                          const __nv_bfloat16* __restrict__ gWl,
                                          int wsOff)
{
    constexpr int COUT = NT * 32;
    constexpr int NCH  = KW / 32;
    constexpr int PL   = COUT * 32;
    constexpr int BUF  = 2 * PL;
    const int tid  = threadIdx.x;
    const int lane = tid & 31;
    const int w    = tid >> 5;
    const int mg   = w & 1;
    const int ng   = w >> 1;

    const int arow = mg * (MT * 16) + (lane & 15);
    const int ac8  = ((lane >> 4) & 1) * 8;
    const __nv_bfloat16* pAh0 = sm + aH + arow * ldA + ac8;
    const __nv_bfloat16* pAl0 = sm + aL + arow * ldA + ac8;
    const int brow = (lane & 7) + ((lane >> 4) & 1) * 8;
    const int bseg = (lane >> 3) & 1;

    auto issue = [&](int ch) {
        __nv_bfloat16* dst = sm + wsOff + (ch & 1) * BUF;
        for (int idx = tid; idx < 2 * COUT * 4; idx += THREADS) {
            int pl = idx >= COUT * 4;
            int j  = idx - pl * COUT * 4;
            int row = j >> 2, s = j & 3;
            const __nv_bfloat16* src = (pl ? gWl : gWh) + row * WSTR + ch * 32 + s * 8;
            CP16(sptr(dst + pl * PL + row * 32 + ((s ^ ((row >> 1) & 3)) << 3)), src);
        }
        asm volatile("cp.async.commit_group;");
    };

    __syncthreads();   // prior users of ring done / prior-stage activations visible
    issue(0);
    if (NCH > 1) issue(1);

#pragma unroll
    for (int ch = 0; ch < NCH; ch++) {
        if (ch < NCH - 1) asm volatile("cp.async.wait_group 1;" ::: "memory");
        else              asm volatile("cp.async.wait_group 0;" ::: "memory");
        __syncthreads();   // chunk ch visible CTA-wide
        const __nv_bfloat16* wb = sm + wsOff + (ch & 1) * BUF;
#pragma unroll
        for (int ks = 0; ks < 32; ks += 16) {
            unsigned ah[MT][4], al[MT][4];
#pragma unroll
            for (int mt = 0; mt < MT; mt++) {
                ldsm4(ah[mt], pAh0 + mt * 16 * ldA + ch * 32 + ks);
                ldsm4(al[mt], pAl0 + mt * 16 * ldA + ch * 32 + ks);
            }
            const int s0 = (ks >> 3) | bseg;
#pragma unroll
            for (int nt = 0; nt < NT; nt += 2) {
                unsigned bh0[4], bl0[4];
                int r0 = ng * (NT * 8) + nt * 8 + brow;
                int o0 = r0 * 32 + ((s0 ^ ((r0 >> 1) & 3)) << 3);
                ldsm4(bh0, wb + o0);
                ldsm4(bl0, wb + PL + o0);
#pragma unroll
                for (int mt = 0; mt < MT; mt++) {
                    mma_bf16(acc[mt][nt], ah[mt], bh0[0], bh0[1]);
                    mma_bf16(acc[mt][nt], al[mt], bh0[0], bh0[1]);
                    mma_bf16(acc[mt][nt], ah[mt], bl0[0], bl0[1]);
                    mma_bf16(acc[mt][nt + 1], ah[mt], bh0[2], bh0[3]);
                    mma_bf16(acc[mt][nt + 1], al[mt], bh0[2], bh0[3]);
                    mma_bf16(acc[mt][nt + 1], ah[mt], bl0[2], bl0[3]);
                }
            }
        }
        if (ch + 2 < NCH) { __syncthreads(); issue(ch + 2); }
    }
}

// relu + split-bf16 smem writeback
template<int MT, int NT>
__device__ __forceinline__ void epilogue_relu(float (*acc)[NT][4], __nv_bfloat16* sm,
                                              int cH, int cL, int ldC)
{
    const int tid  = threadIdx.x;
    const int lane = tid & 31;
    const int w    = tid >> 5;
    const int g    = lane >> 2;
    const int t    = lane & 3;
    const int mg   = w & 1;
    const int ng   = w >> 1;
    __nv_bfloat16* sCh = sm + cH;
    __nv_bfloat16* sCl = sm + cL;
#pragma unroll
    for (int mt = 0; mt < MT; mt++) {
#pragma unroll
        for (int nt = 0; nt < NT; nt++) {
            int n0 = ng * (NT * 8) + nt * 8 + 2 * t;
            int r = mg * (MT * 16) + mt * 16 + g;
            float v0 = fmaxf(acc[mt][nt][0], 0.0f);
            float v1 = fmaxf(acc[mt][nt][1], 0.0f);
            float v2 = fmaxf(acc[mt][nt][2], 0.0f);
            float v3 = fmaxf(acc[mt][nt][3], 0.0f);
            __nv_bfloat16 h0 = __float2bfloat16(v0), h1 = __float2bfloat16(v1);
            __nv_bfloat16 h2 = __float2bfloat16(v2), h3 = __float2bfloat16(v3);
            __nv_bfloat16 l0 = __float2bfloat16(v0 - __bfloat162float(h0));
            __nv_bfloat16 l1 = __float2bfloat16(v1 - __bfloat162float(h1));
            __nv_bfloat16 l2 = __float2bfloat16(v2 - __bfloat162float(h2));
            __nv_bfloat16 l3 = __float2bfloat16(v3 - __bfloat162float(h3));
            *(unsigned*)(sCh + r * ldC + n0)       = pack2(h0, h1);
            *(unsigned*)(sCh + (r + 8) * ldC + n0) = pack2(h2, h3);
            *(unsigned*)(sCl + r * ldC + n0)       = pack2(l0, l1);
            *(unsigned*)(sCl + (r + 8) * ldC + n0) = pack2(l2, l3);
        }
    }
}

// acc init: bias (+ optional per-cluster p2l gather)
template<int MT, int NT, int JSTR>
__device__ __forceinline__ void init_acc(float (*acc)[NT][4], const float* gBias,
                                         const float* p2l, const int* s_cl)
{
    const int tid  = threadIdx.x;
    const int lane = tid & 31;
    const int w    = tid >> 5;
    const int g    = lane >> 2;
    const int t    = lane & 3;
    const int mg   = w & 1;
    const int ng   = w >> 1;
#pragma unroll
    for (int mt = 0; mt < MT; mt++) {
#pragma unroll
        for (int nt = 0; nt < NT; nt++) {
            int n0 = ng * (NT * 8) + nt * 8 + 2 * t;
            float b0 = gBias ? gBias[n0] : 0.0f;
            float b1 = gBias ? gBias[n0 + 1] : 0.0f;
            if (JSTR) {
                int r = mg * (MT * 16) + mt * 16 + g;
                int c0 = s_cl[r], c1 = s_cl[r + 8];
                acc[mt][nt][0] = b0 + p2l[c0 * JSTR + n0];
                acc[mt][nt][1] = b1 + p2l[c0 * JSTR + n0 + 1];
                acc[mt][nt][2] = b0 + p2l[c1 * JSTR + n0];
                acc[mt][nt][3] = b1 + p2l[c1 * JSTR + n0 + 1];
            } else {
                acc[mt][nt][0] = b0; acc[mt][nt][1] = b1;
                acc[mt][nt][2] = b0; acc[mt][nt][3] = b1;
            }
        }
    }
}

template<int MT, int NT, int KW, int WSTR, int JSTR>
__device__ void gemm2(__nv_bfloat16* sm, int aH, int aL, int ldA,
                      const __nv_bfloat16* __restrict__ gWh,
                      const __nv_bfloat16* __restrict__ gWl,
                      const float* __restrict__ gBias,
                      const float* __restrict__ p2l, const int* __restrict__ s_cl,
                      int cH, int cL, int ldC, int wsOff)
{
    float acc[MT][NT][4];
    init_acc<MT, NT, JSTR>(acc, gBias, p2l, s_cl);
    gemm_core<MT, NT, KW, WSTR>(acc, sm, aH, aL, ldA, gWh, gWl, wsOff);
    epilogue_relu<MT, NT>(acc, sm, cH, cL, ldC);
}

// final GEMM: relu -> per-column tile max -> global atomicMax
template<int MT, int NT, int KW, int WSTR>
__device__ void gemm_out(__nv_bfloat16* sm, int aH, int aL, int ldA,
                         const __nv_bfloat16* __restrict__ gWh,
                         const __nv_bfloat16* __restrict__ gWl,
                         const float* __restrict__ gBias,
                         float* __restrict__ outb, int wsOff)
{
    const int lane = threadIdx.x & 31;
    const int t    = lane & 3;
    const int ng   = (threadIdx.x >> 5) >> 1;

    float acc[MT][NT][4];
    init_acc<MT, NT, 0>(acc, gBias, nullptr, nullptr);
    gemm_core<MT, NT, KW, WSTR>(acc, sm, aH, aL, ldA, gWh, gWl, wsOff);

#pragma unroll
    for (int nt = 0; nt < NT; nt++) {
        int n0 = ng * (NT * 8) + nt * 8 + 2 * t;
        float m0 = 0.0f, m1 = 0.0f;
#pragma unroll
        for (int mt = 0; mt < MT; mt++) {
            m0 = fmaxf(m0, fmaxf(acc[mt][nt][0], acc[mt][nt][2]));
            m1 = fmaxf(m1, fmaxf(acc[mt][nt][1], acc[mt][nt][3]));
        }
#pragma unroll
        for (int o = 4; o < 32; o <<= 1) {
            m0 = fmaxf(m0, __shfl_xor_sync(0xffffffff, m0, o));
            m1 = fmaxf(m1, __shfl_xor_sync(0xffffffff, m1, o));
        }
        if ((lane >> 2) == 0) {
            atomicMax((int*)&outb[n0],     __float_as_int(m0));
            atomicMax((int*)&outb[n0 + 1], __float_as_int(m1));
        }
    }
}

// ---------------- feature store + segment-max pool ----------------
__device__ void store_and_pool(__nv_bfloat16* sm, const int* s_cl, int nc, int b,
                               unsigned* __restrict__ gfeat, float* __restrict__ gpool,
                               int P0, int qH, int qL, int ldQ, float* spool)
{
    const int tid = threadIdx.x;
    for (int i = tid; i < TILE * 128; i += THREADS) {
        int p = i >> 7, c = i & 127;
        unsigned h = (unsigned)__bfloat16_as_ushort(sm[qH + p * ldQ + c]);
        unsigned l = (unsigned)__bfloat16_as_ushort(sm[qL + p * ldQ + c]);
        gfeat[(size_t)(P0 + p) * 128 + c] = h | (l << 16);
    }
    for (int i = tid; i < nc * 128; i += THREADS) spool[i] = 0.0f;
    __syncthreads();
    for (int i = tid; i < TILE * 128; i += THREADS) {
        int p = i >> 7, c = i & 127;
        float v = __bfloat162float(sm[qH + p * ldQ + c]) +
                  __bfloat162float(sm[qL + p * ldQ + c]);
        atomicMax((int*)&spool[s_cl[p] * 128 + c], __float_as_int(v));
    }
    __syncthreads();
    for (int i = tid; i < nc * 128; i += THREADS) {
        float v = spool[i];
        if (v > 0.0f)
            atomicMax((int*)&gpool[b * (64 * 128) + i], __float_as_int(v));
    }
}

// ---------------- K0: split-K, M=128 ----------------
__global__ void __launch_bounds__(THREADS)
k0_kernel(const float* __restrict__ x, const int* __restrict__ clusters,
          const float* __restrict__ b_in, const float* __restrict__ b1,
          const float* __restrict__ b2,
          unsigned* __restrict__ gfeat, float* __restrict__ gpool)
{
    extern __shared__ __nv_bfloat16 sm[];
    int* s_cl = (int*)(sm + K0_END);
    const int tid = threadIdx.x;
    const int P0  = blockIdx.x * TILE;
    const int b   = P0 / NPTS;

    for (int i = tid; i < TILE * 32; i += THREADS) {
        int p = i >> 5, k = i & 31;
        float v = (k < 28) ? x[(size_t)(P0 + p) * 28 + k] : 0.0f;
        __nv_bfloat16 h = __float2bfloat16(v);
        sm[K0_X_H + p * LD_40 + k] = h;
        sm[K0_X_L + p * LD_40 + k] = __float2bfloat16(v - __bfloat162float(h));
    }
    if (tid < TILE) s_cl[tid] = clusters[P0 + tid];

    float acc1[4][2][4];
    init_acc<4, 2, 0>(acc1, b1, nullptr, nullptr);

    gemm2<4, 4, 32, 32, 0>(sm, K0_X_H, K0_X_L, LD_40, g_wh + OFF_WIN, g_wl + OFF_WIN,
                           b_in, nullptr, nullptr, K0_C_H, K0_C_L, LD_136, K0_WS);
    gemm_core<4, 2, 128, 256>(acc1, sm, K0_C_H, K0_C_L, LD_136,
                              g_wh + OFF_W1, g_wl + OFF_W1, K0_WS);
    gemm2<4, 4, 32, 32, 0>(sm, K0_X_H, K0_X_L, LD_40,
                           g_wh + OFF_WIN + 128 * 32, g_wl + OFF_WIN + 128 * 32,
                           b_in + 128, nullptr, nullptr, K0_C_H, K0_C_L, LD_136, K0_WS);
    gemm_core<4, 2, 128, 256>(acc1, sm, K0_C_H, K0_C_L, LD_136,
                              g_wh + OFF_W1 + 128, g_wl + OFF_W1 + 128, K0_WS);
    epilogue_relu<4, 2>(acc1, sm, K0_M_H, K0_M_L, LD_72);

    gemm2<4, 4, 64, 64, 0>(sm, K0_M_H, K0_M_L, LD_72, g_wh + OFF_W2, g_wl + OFF_W2,
                           b2, nullptr, nullptr, K0_IO_H, K0_IO_L, LD_136, K0_WS);
    __syncthreads();

    store_and_pool(sm, s_cl, 16, b, gfeat, gpool, P0, K0_IO_H, K0_IO_L, LD_136,
                   (float*)(sm + K0_WS));
}

// ---------------- mid: conv3 (P->Q), conv1 (Q+p2l->M), conv2 (M->Q) ----------------
__global__ void __launch_bounds__(THREADS)
mid_kernel(const unsigned* __restrict__ fin, unsigned* __restrict__ fout,
           const int* __restrict__ cl_in, const int* __restrict__ cl_out,
           int nc_in, float* __restrict__ gpool_out, int nc_out,
           const __nv_bfloat16* __restrict__ wh3, const __nv_bfloat16* __restrict__ wl3,
           const float* __restrict__ b3,
           const __nv_bfloat16* __restrict__ wh1, const __nv_bfloat16* __restrict__ wl1,
           const __nv_bfloat16* __restrict__ wh2, const __nv_bfloat16* __restrict__ wl2,
           const float* __restrict__ b2)
{
    extern __shared__ __nv_bfloat16 sm[];
    int* s_cl = (int*)(sm + MF_END);
    const int tid = threadIdx.x;
    const int P0  = blockIdx.x * TILE;
    const int b   = P0 / NPTS;

    for (int i = tid; i < TILE * 128; i += THREADS) {
        int p = i >> 7, c = i & 127;
        unsigned u = fin[(size_t)(P0 + p) * 128 + c];
        sm[MF_P_H + p * LD_136 + c] = __ushort_as_bfloat16((unsigned short)(u & 0xffff));
        sm[MF_P_L + p * LD_136 + c] = __ushort_as_bfloat16((unsigned short)(u >> 16));
    }
    if (tid < TILE) s_cl[tid] = cl_in[P0 + tid];
    else s_cl[tid] = cl_out[P0 + tid - TILE];

    const float* p2l_b = g_p2l + b * nc_in * 64;

    gemm2<4, 4, 128, 128, 0>(sm, MF_P_H, MF_P_L, LD_136, wh3, wl3, b3,
                             nullptr, nullptr, MF_Q_H, MF_Q_L, LD_136, MF_WS);
    gemm2<4, 2, 128, 256, 64>(sm, MF_Q_H, MF_Q_L, LD_136, wh1, wl1, nullptr,
                              p2l_b, s_cl, MF_M_H, MF_M_L, LD_72, MF_WS);
    gemm2<4, 4, 64, 64, 0>(sm, MF_M_H, MF_M_L, LD_72, wh2, wl2, b2,
                           nullptr, nullptr, MF_Q_H, MF_Q_L, LD_136, MF_WS);
    __syncthreads();

    store_and_pool(sm, s_cl + TILE, nc_out, b, fout, gpool_out, P0, MF_Q_H, MF_Q_L, LD_136,
                   (float*)(sm + MF_M_H));
}

// ---------------- final: conv3 (P->Q), out1 (Q+p2l->P), out2 (P->max->out) ----------------
__global__ void __launch_bounds__(THREADS)
final_kernel(const unsigned* __restrict__ fin, const int* __restrict__ cl_in,
             const __nv_bfloat16* __restrict__ wh3, const __nv_bfloat16* __restrict__ wl3,
             const float* __restrict__ b3,
             const float* __restrict__ bo2,
             float* __restrict__ out)
{
    extern __shared__ __nv_bfloat16 sm[];
    int* s_cl = (int*)(sm + MF_END);
    const int tid = threadIdx.x;
    const int P0  = blockIdx.x * TILE;
    const int b   = P0 / NPTS;

    for (int i = tid; i < TILE * 128; i += THREADS) {
        int p = i >> 7, c = i & 127;
        unsigned u = fin[(size_t)(P0 + p) * 128 + c];
        sm[MF_P_H + p * LD_136 + c] = __ushort_as_bfloat16((unsigned short)(u & 0xffff));
        sm[MF_P_L + p * LD_136 + c] = __ushort_as_bfloat16((unsigned short)(u >> 16));
    }
    if (tid < TILE) s_cl[tid] = cl_in[P0 + tid];

    const float* p2l_b = g_p2l + b * 64 * 128;

    gemm2<4, 4, 128, 128, 0>(sm, MF_P_H, MF_P_L, LD_136, wh3, wl3, b3,
                             nullptr, nullptr, MF_Q_H, MF_Q_L, LD_136, MF_WS);
    gemm2<4, 4, 128, 256, 128>(sm, MF_Q_H, MF_Q_L, LD_136, g_wh + OFF_WO1, g_wl + OFF_WO1,
                               nullptr, p2l_b, s_cl, MF_P_H, MF_P_L, LD_136, MF_WS);
    gemm_out<4, 4, 128, 128>(sm, MF_P_H, MF_P_L, LD_136, g_wh + OFF_WO2, g_wl + OFF_WO2,
                             bo2, out + b * 128, MF_WS);
}

extern "C" void kernel_launch(void* const* d_in, const int* in_sizes, int n_in,
                              void* d_out, int out_size)
{
    const float* x    = (const float*)d_in[0];
    const int*   cl   = (const int*)  d_in[1];
    const float* w_in = (const float*)d_in[2];
    const float* b_in = (const float*)d_in[3];
    const float* w1   = (const float*)d_in[4];
    const float* b1   = (const float*)d_in[5];
    const float* w2   = (const float*)d_in[6];
    const float* b2   = (const float*)d_in[7];
    const float* w3   = (const float*)d_in[8];
    const float* b3   = (const float*)d_in[9];
    const float* wo1  = (const float*)d_in[10];
    const float* bo1  = (const float*)d_in[11];
    const float* wo2  = (const float*)d_in[12];
    const float* bo2  = (const float*)d_in[13];
    float* out = (float*)d_out;

    void *pa_, *pb_, *pp_, *ph_, *pl_, *pq_;
    cudaGetSymbolAddress(&pa_, g_featA);
    cudaGetSymbolAddress(&pb_, g_featB);
    cudaGetSymbolAddress(&pp_, g_pool);
    cudaGetSymbolAddress(&ph_, g_wh);
    cudaGetSymbolAddress(&pl_, g_wl);
    cudaGetSymbolAddress(&pq_, g_p2l);
    unsigned* fA = (unsigned*)pa_;
    unsigned* fB = (unsigned*)pb_;
    float* pP = (float*)pp_;
    float* pQ = (float*)pq_;
    __nv_bfloat16* wh = (__nv_bfloat16*)ph_;
    __nv_bfloat16* wl = (__nv_bfloat16*)pl_;

    cudaFuncSetAttribute(k0_kernel,    cudaFuncAttributeMaxDynamicSharedMemorySize, SMEM_K0);
    cudaFuncSetAttribute(mid_kernel,   cudaFuncAttributeMaxDynamicSharedMemorySize, SMEM_MF);
    cudaFuncSetAttribute(final_kernel, cudaFuncAttributeMaxDynamicSharedMemorySize, SMEM_MF);

    const int PSTRIDE = BATCH * 64 * 128;

    init_kernel<<<(3 * PSTRIDE + 255) / 256, 256>>>(out);
    convert_all<<<(180224 + 255) / 256, 256>>>(w_in, w1, w2, w3, wo1, wo2);
    warm_kernel<<<1, 32>>>();

    k0_kernel<<<NTILES, THREADS, SMEM_K0>>>(x, cl, b_in, b1, b2, fA, pP);

    p2l_kernel<<<8 * 16, 128>>>(w1 + 1 * 64 * 256, b1 + 64, pP, pQ, 16, 64);
    mid_kernel<<<NTILES, THREADS, SMEM_MF>>>(
        fA, fB, cl, cl + BN, 16, pP + PSTRIDE, 32,
        wh + OFF_W3, wl + OFF_W3, b3,
        wh + OFF_W1 + 64 * 256, wl + OFF_W1 + 64 * 256,
        wh + OFF_W2 + 128 * 64, wl + OFF_W2 + 128 * 64, b2 + 128);

    p2l_kernel<<<8 * 32, 128>>>(w1 + 2 * 64 * 256, b1 + 128, pP + PSTRIDE, pQ, 32, 64);
    mid_kernel<<<NTILES, THREADS, SMEM_MF>>>(
        fB, fA, cl + BN, cl + 2 * BN, 32, pP + 2 * PSTRIDE, 64,
        wh + OFF_W3 + 128 * 128, wl + OFF_W3 + 128 * 128, b3 + 128,
        wh + OFF_W1 + 2 * 64 * 256, wl + OFF_W1 + 2 * 64 * 256,
        wh + OFF_W2 + 2 * 128 * 64, wl + OFF_W2 + 2 * 128 * 64, b2 + 2 * 128);

    p2l_kernel<<<8 * 64, 128>>>(wo1, bo1, pP + 2 * PSTRIDE, pQ, 64, 128);
    final_kernel<<<NTILES, THREADS, SMEM_MF>>>(
        fA, cl + 2 * BN,
        wh + OFF_W3 + 2 * 128 * 128, wl + OFF_W3 + 2 * 128 * 128, b3 + 2 * 128,
        bo2, out);
}

// round 15
// speedup vs baseline: 1.2796x; 1.2796x over previous
#include <cuda_runtime.h>
#include <cuda_bf16.h>

#define BATCH   8
#define NPTS    16384
#define BN      (BATCH * NPTS)
#define TILE    64
#define NTILES  (BN / TILE)        // 2048
#define THREADS 256                // 8 warps: 2 m-groups(32 rows) x 4 n-groups

// ---------------- mid/final smem layout (bf16 units) ----------------
#define MF_P_H  0                  // 64x136
#define MF_P_L  8704
#define MF_Q_H  17408              // 64x136
#define MF_Q_L  26112
#define MF_WS   34816              // weight ring: 2 bufs (32KB)
#define MF_END  51200
#define SMEM_MF (MF_END*2 + 512)   // 102912 B -> 2 CTAs/SM

// ---------------- k0 smem layout ----------------
#define K0_X_H  0                  // 64x40
#define K0_X_L  2560
#define K0_C_H  5120               // 64x136 (half of mlp_in output; reused)
#define K0_C_L  13824
#define K0_M_H  22528              // 64x72 (conv1 out)
#define K0_M_L  27136
#define K0_IO_H 5120               // conv2 out overlays C
#define K0_IO_L 13824
#define K0_WS   31744              // 3-buffer ring: 24576 elems (48KB)
#define K0_END  56320
#define SMEM_K0 (K0_END*2 + 512)   // 113152 B -> 2 CTAs/SM

#define LD_136 136
#define LD_72  72
#define LD_40  40

// ---------------- global scratch ----------------
__device__ unsigned g_featA[BN * 128];
__device__ unsigned g_featB[BN * 128];
__device__ float    g_pool[3 * BATCH * 64 * 128];
__device__ float    g_p2l[8 * 64 * 128];
__device__ __nv_bfloat16 g_wh[180224];
__device__ __nv_bfloat16 g_wl[180224];

#define OFF_WIN 0        // 256 x 32
#define OFF_W1  8192     // 3 x (64 x 256)
#define OFF_W2  57344    // 3 x (128 x 64)
#define OFF_W3  81920    // 3 x (128 x 128)
#define OFF_WO1 131072   // 128 x 256
#define OFF_WO2 163840   // 128 x 128

__global__ void init_kernel(float* __restrict__ out) {
    int i = blockIdx.x * blockDim.x + threadIdx.x;
    if (i < 3 * BATCH * 64 * 128) g_pool[i] = 0.0f;
    if (i < BATCH * 128) out[i] = 0.0f;
}

__global__ void warm_kernel() {}

__global__ void convert_all(const float* __restrict__ w_in, const float* __restrict__ w1,
                            const float* __restrict__ w2, const float* __restrict__ w3,
                            const float* __restrict__ wo1, const float* __restrict__ wo2) {
    int i = blockIdx.x * blockDim.x + threadIdx.x;
    if (i >= 180224) return;
    const float* src; int base, cin, kpad;
    if (i < 8192)        { src = w_in; base = 0;      cin = 28;  kpad = 32;  }
    else if (i < 57344)  { src = w1;   base = 8192;   cin = 256; kpad = 256; }
    else if (i < 81920)  { src = w2;   base = 57344;  cin = 64;  kpad = 64;  }
    else if (i < 131072) { src = w3;   base = 81920;  cin = 128; kpad = 128; }
    else if (i < 163840) { src = wo1;  base = 131072; cin = 256; kpad = 256; }
    else                 { src = wo2;  base = 163840; cin = 128; kpad = 128; }
    int j = i - base, r = j / kpad, k = j - r * kpad;
    float v = (k < cin) ? src[r * cin + k] : 0.0f;
    __nv_bfloat16 h = __float2bfloat16(v);
    g_wh[i] = h;
    g_wl[i] = __float2bfloat16(v - __bfloat162float(h));
}

// p2l[b][cl][j] = bias[j] + W[j][128..255] . pool[b][cl][:]
__global__ void p2l_kernel(const float* __restrict__ w, const float* __restrict__ bias,
                           const float* __restrict__ pool, float* __restrict__ dst,
                           int ncl, int J) {
    __shared__ float sp[128];
    int bc = blockIdx.x;
    int b = bc / ncl, cl = bc - b * ncl;
    sp[threadIdx.x] = pool[b * 8192 + cl * 128 + threadIdx.x];
    __syncthreads();
    for (int j = threadIdx.x; j < J; j += 128) {
        const float4* wr = (const float4*)(w + j * 256 + 128);
        float s = bias[j];
#pragma unroll
        for (int k = 0; k < 32; k++) {
            float4 wv = wr[k];
            float4 pv = ((const float4*)sp)[k];
            s += wv.x * pv.x + wv.y * pv.y + wv.z * pv.z + wv.w * pv.w;
        }
        dst[bc * J + j] = s;
    }
}

// ---------------- helpers ----------------
__device__ __forceinline__ void mma_bf16(float c[4], const unsigned a[4],
                                         unsigned b0, unsigned b1) {
    asm volatile(
        "mma.sync.aligned.m16n8k16.row.col.f32.bf16.bf16.f32 "
        "{%0,%1,%2,%3}, {%4,%5,%6,%7}, {%8,%9}, {%0,%1,%2,%3};"
        : "+f"(c[0]), "+f"(c[1]), "+f"(c[2]), "+f"(c[3])
        : "r"(a[0]), "r"(a[1]), "r"(a[2]), "r"(a[3]), "r"(b0), "r"(b1));
}
__device__ __forceinline__ unsigned sptr(const void* p) {
    return (unsigned)__cvta_generic_to_shared(p);
}
__device__ __forceinline__ void ldsm4(unsigned r[4], const void* p) {
    asm volatile("ldmatrix.sync.aligned.m8n8.x4.shared.b16 {%0,%1,%2,%3}, [%4];"
                 : "=r"(r[0]), "=r"(r[1]), "=r"(r[2]), "=r"(r[3]) : "r"(sptr(p)));
}
__device__ __forceinline__ unsigned pack2(__nv_bfloat16 x, __nv_bfloat16 y) {
    return ((unsigned)__bfloat16_as_ushort(y) << 16) | (unsigned)__bfloat16_as_ushort(x);
}
#define CP16(d, s) asm volatile("cp.async.cg.shared.global [%0], [%1], 16;" :: "r"(d), "l"(s))

// stage one KC=32 chunk of weights [cout x 32] (both planes) at base, 64B rows,
// XOR swizzle seg^=(row>>1)&3 (conflict-free ldmatrix + cp.async)
__device__ __forceinline__ void stage_chunk(__nv_bfloat16* base,
        const __nv_bfloat16* __restrict__ wh, const __nv_bfloat16* __restrict__ wl,
        int wstr, int cout, int kcol)
{
    const int tid = threadIdx.x;
    const int pl_elems = cout * 32;
    for (int idx = tid; idx < 2 * cout * 4; idx += THREADS) {
        int pl = idx >= cout * 4;
        int j  = idx - pl * cout * 4;
        int row = j >> 2, s = j & 3;
        const __nv_bfloat16* src = (pl ? wl : wh) + row * wstr + kcol + s * 8;
        CP16(sptr(base + pl * pl_elems + row * 32 + ((s ^ ((row >> 1) & 3)) << 3)), src);
    }
    asm volatile("cp.async.commit_group;");
}

// ================= GEMM mainloop: KC=32, RING-buffered compact weights =================
// 8 warps: 2 m-groups(32 rows) x 4 n-groups. acc[2][NT][4].
// RING=2: pre-issue needs barrier; RING=3: no barrier before issue(ch+2).
// PRE: chunk0 was prefetched by the previous layer (skip issue(0)).
// nx*: if nxCOUT>0 and NCH even, prefetch next layer's chunk0 during last chunk.
template<int NT, int KW, int WSTR, int RING, bool PRE>
__device__ __forceinline__ void gemm_core(float (*acc)[NT][4], __nv_bfloat16* sm,
                                          int aH, int aL, int ldA,
                                          const __nv_bfloat16* __restrict__ gWh,
                                          const __nv_bfloat16* __restrict__ gWl,
                                          int wsOff,
                                          const __nv_bfloat16* nxWh = nullptr,
                                          const __nv_bfloat16* nxWl = nullptr,
                                          int nxWSTR = 0, int nxCOUT = 0)
{
    constexpr int COUT = NT * 32;
    constexpr int NCH  = KW / 32;
    constexpr int PL   = COUT * 32;
    constexpr int BUF  = 2 * PL;
    const int tid  = threadIdx.x;
    const int lane = tid & 31;
    const int w    = tid >> 5;
    const int mg   = w & 1;
    const int ng   = w >> 1;

    const int arow = mg * 32 + (lane & 15);
    const int ac8  = ((lane >> 4) & 1) * 8;
    const __nv_bfloat16* pAh0 = sm + aH + arow * ldA + ac8;
    const __nv_bfloat16* pAl0 = sm + aL + arow * ldA + ac8;
    const int brow = (lane & 7) + ((lane >> 4) & 1) * 8;
    const int bseg = (lane >> 3) & 1;

    __syncthreads();   // prior users of ring done / prior-stage activations visible
    if (!PRE) stage_chunk(sm + wsOff, gWh, gWl, WSTR, COUT, 0);
    if (NCH > 1) stage_chunk(sm + wsOff + (1 % RING) * BUF, gWh, gWl, WSTR, COUT, 32);

#pragma unroll
    for (int ch = 0; ch < NCH; ch++) {
        if (ch < NCH - 1) asm volatile("cp.async.wait_group 1;" ::: "memory");
        else              asm volatile("cp.async.wait_group 0;" ::: "memory");
        __syncthreads();   // chunk ch visible CTA-wide
        // cross-layer prefetch: next layer's chunk0 into buffer 0 (free: readers on buf1)
        if (RING == 2 && (NCH % 2 == 0) && ch == NCH - 1 && nxCOUT > 0)
            stage_chunk(sm + wsOff, nxWh, nxWl, nxWSTR, nxCOUT, 0);
        const __nv_bfloat16* wb = sm + wsOff + (ch % RING) * BUF;
#pragma unroll
        for (int ks = 0; ks < 32; ks += 16) {
            unsigned ah[2][4], al[2][4];
            ldsm4(ah[0], pAh0 + ch * 32 + ks);
            ldsm4(al[0], pAl0 + ch * 32 + ks);
            ldsm4(ah[1], pAh0 + 16 * ldA + ch * 32 + ks);
            ldsm4(al[1], pAl0 + 16 * ldA + ch * 32 + ks);
            const int s0 = (ks >> 3) | bseg;
#pragma unroll
            for (int nt = 0; nt < NT; nt += 2) {
                unsigned bh0[4], bl0[4];
                int r0 = ng * (NT * 8) + nt * 8 + brow;
                int o0 = r0 * 32 + ((s0 ^ ((r0 >> 1) & 3)) << 3);
                ldsm4(bh0, wb + o0);
                ldsm4(bl0, wb + PL + o0);
#pragma unroll
                for (int mt = 0; mt < 2; mt++) {
                    mma_bf16(acc[mt][nt], ah[mt], bh0[0], bh0[1]);
                    mma_bf16(acc[mt][nt], al[mt], bh0[0], bh0[1]);
                    mma_bf16(acc[mt][nt], ah[mt], bl0[0], bl0[1]);
                    mma_bf16(acc[mt][nt + 1], ah[mt], bh0[2], bh0[3]);
                    mma_bf16(acc[mt][nt + 1], al[mt], bh0[2], bh0[3]);
                    mma_bf16(acc[mt][nt + 1], ah[mt], bl0[2], bl0[3]);
                }
            }
        }
        if (ch + 2 < NCH) {
            if (RING == 2) __syncthreads();   // RING=3: target buffer provably free
            stage_chunk(sm + wsOff + ((ch + 2) % RING) * BUF, gWh, gWl, WSTR, COUT, (ch + 2) * 32);
        }
    }
}

// relu + split-bf16 smem writeback
template<int NT>
__device__ __forceinline__ void epilogue_relu(float (*acc)[NT][4], __nv_bfloat16* sm,
                                              int cH, int cL, int ldC)
{
    const int tid  = threadIdx.x;
    const int lane = tid & 31;
    const int w    = tid >> 5;
    const int g    = lane >> 2;
    const int t    = lane & 3;
    const int mg   = w & 1;
    const int ng   = w >> 1;
    __nv_bfloat16* sCh = sm + cH;
    __nv_bfloat16* sCl = sm + cL;
#pragma unroll
    for (int mt = 0; mt < 2; mt++) {
#pragma unroll
        for (int nt = 0; nt < NT; nt++) {
            int n0 = ng * (NT * 8) + nt * 8 + 2 * t;
            int r = mg * 32 + mt * 16 + g;
            float v0 = fmaxf(acc[mt][nt][0], 0.0f);
            float v1 = fmaxf(acc[mt][nt][1], 0.0f);
            float v2 = fmaxf(acc[mt][nt][2], 0.0f);
            float v3 = fmaxf(acc[mt][nt][3], 0.0f);
            __nv_bfloat16 h0 = __float2bfloat16(v0), h1 = __float2bfloat16(v1);
            __nv_bfloat16 h2 = __float2bfloat16(v2), h3 = __float2bfloat16(v3);
            __nv_bfloat16 l0 = __float2bfloat16(v0 - __bfloat162float(h0));
            __nv_bfloat16 l1 = __float2bfloat16(v1 - __bfloat162float(h1));
            __nv_bfloat16 l2 = __float2bfloat16(v2 - __bfloat162float(h2));
            __nv_bfloat16 l3 = __float2bfloat16(v3 - __bfloat162float(h3));
            *(unsigned*)(sCh + r * ldC + n0)       = pack2(h0, h1);
            *(unsigned*)(sCh + (r + 8) * ldC + n0) = pack2(h2, h3);
            *(unsigned*)(sCl + r * ldC + n0)       = pack2(l0, l1);
            *(unsigned*)(sCl + (r + 8) * ldC + n0) = pack2(l2, l3);
        }
    }
}

// acc init: bias (+ optional per-cluster p2l gather)
template<int NT, int JSTR>
__device__ __forceinline__ void init_acc(float (*acc)[NT][4], const float* gBias,
                                         const float* p2l, const int* s_cl)
{
    const int tid  = threadIdx.x;
    const int lane = tid & 31;
    const int w    = tid >> 5;
    const int g    = lane >> 2;
    const int t    = lane & 3;
    const int mg   = w & 1;
    const int ng   = w >> 1;
#pragma unroll
    for (int mt = 0; mt < 2; mt++) {
#pragma unroll
        for (int nt = 0; nt < NT; nt++) {
            int n0 = ng * (NT * 8) + nt * 8 + 2 * t;
            float b0 = gBias ? gBias[n0] : 0.0f;
            float b1 = gBias ? gBias[n0 + 1] : 0.0f;
            if (JSTR) {
                int c0 = s_cl[mg * 32 + mt * 16 + g];
                int c1 = s_cl[mg * 32 + mt * 16 + g + 8];
                acc[mt][nt][0] = b0 + p2l[c0 * JSTR + n0];
                acc[mt][nt][1] = b1 + p2l[c0 * JSTR + n0 + 1];
                acc[mt][nt][2] = b0 + p2l[c1 * JSTR + n0];
                acc[mt][nt][3] = b1 + p2l[c1 * JSTR + n0 + 1];
            } else {
                acc[mt][nt][0] = b0; acc[mt][nt][1] = b1;
                acc[mt][nt][2] = b0; acc[mt][nt][3] = b1;
            }
        }
    }
}

template<int NT, int KW, int WSTR, int JSTR, int RING, bool PRE>
__device__ void gemm2(__nv_bfloat16* sm, int aH, int aL, int ldA,
                      const __nv_bfloat16* __restrict__ gWh,
                      const __nv_bfloat16* __restrict__ gWl,
                      const float* __restrict__ gBias,
                      const float* __restrict__ p2l, const int* __restrict__ s_cl,
                      int cH, int cL, int ldC, int wsOff,
                      const __nv_bfloat16* nxWh = nullptr,
                      const __nv_bfloat16* nxWl = nullptr,
                      int nxWSTR = 0, int nxCOUT = 0)
{
    float acc[2][NT][4];
    init_acc<NT, JSTR>(acc, gBias, p2l, s_cl);
    gemm_core<NT, KW, WSTR, RING, PRE>(acc, sm, aH, aL, ldA, gWh, gWl, wsOff,
                                       nxWh, nxWl, nxWSTR, nxCOUT);
    epilogue_relu<NT>(acc, sm, cH, cL, ldC);
}

// final GEMM: relu -> per-column tile max -> global atomicMax
template<int NT, int KW, int WSTR, bool PRE>
__device__ void gemm_out(__nv_bfloat16* sm, int aH, int aL, int ldA,
                         const __nv_bfloat16* __restrict__ gWh,
                         const __nv_bfloat16* __restrict__ gWl,
                         const float* __restrict__ gBias,
                         float* __restrict__ outb, int wsOff)
{
    const int lane = threadIdx.x & 31;
    const int t    = lane & 3;
    const int ng   = (threadIdx.x >> 5) >> 1;

    float acc[2][NT][4];
    init_acc<NT, 0>(acc, gBias, nullptr, nullptr);
    gemm_core<NT, KW, WSTR, 2, PRE>(acc, sm, aH, aL, ldA, gWh, gWl, wsOff);

#pragma unroll
    for (int nt = 0; nt < NT; nt++) {
        int n0 = ng * (NT * 8) + nt * 8 + 2 * t;
        float m0 = 0.0f, m1 = 0.0f;
#pragma unroll
        for (int mt = 0; mt < 2; mt++) {
            m0 = fmaxf(m0, fmaxf(acc[mt][nt][0], acc[mt][nt][2]));
            m1 = fmaxf(m1, fmaxf(acc[mt][nt][1], acc[mt][nt][3]));
        }
#pragma unroll
        for (int o = 4; o < 32; o <<= 1) {
            m0 = fmaxf(m0, __shfl_xor_sync(0xffffffff, m0, o));
            m1 = fmaxf(m1, __shfl_xor_sync(0xffffffff, m1, o));
        }
        if ((lane >> 2) == 0) {
            atomicMax((int*)&outb[n0],     __float_as_int(m0));
            atomicMax((int*)&outb[n0 + 1], __float_as_int(m1));
        }
    }
}

// ---------------- feature store + segment-max pool ----------------
__device__ void store_and_pool(__nv_bfloat16* sm, const int* s_cl, int nc, int b,
                               unsigned* __restrict__ gfeat, float* __restrict__ gpool,
                               int P0, int qH, int qL, int ldQ, float* spool)
{
    const int tid = threadIdx.x;
    for (int i = tid; i < TILE * 128; i += THREADS) {
        int p = i >> 7, c = i & 127;
        unsigned h = (unsigned)__bfloat16_as_ushort(sm[qH + p * ldQ + c]);
        unsigned l = (unsigned)__bfloat16_as_ushort(sm[qL + p * ldQ + c]);
        gfeat[(size_t)(P0 + p) * 128 + c] = h | (l << 16);
    }
    for (int i = tid; i < nc * 128; i += THREADS) spool[i] = 0.0f;
    __syncthreads();
    for (int i = tid; i < TILE * 128; i += THREADS) {
        int p = i >> 7, c = i & 127;
        float v = __bfloat162float(sm[qH + p * ldQ + c]) +
                  __bfloat162float(sm[qL + p * ldQ + c]);
        atomicMax((int*)&spool[s_cl[p] * 128 + c], __float_as_int(v));
    }
    __syncthreads();
    for (int i = tid; i < nc * 128; i += THREADS) {
        float v = spool[i];
        if (v > 0.0f)
            atomicMax((int*)&gpool[b * (64 * 128) + i], __float_as_int(v));
    }
}

// ---------------- K0: split-K (3-buffer ring, barrier-light staging) ----------------
__global__ void __launch_bounds__(THREADS, 2)
k0_kernel(const float* __restrict__ x, const int* __restrict__ clusters,
          const float* __restrict__ b_in, const float* __restrict__ b1,
          const float* __restrict__ b2,
          unsigned* __restrict__ gfeat, float* __restrict__ gpool)
{
    extern __shared__ __nv_bfloat16 sm[];
    int* s_cl = (int*)(sm + K0_END);
    const int tid = threadIdx.x;
    const int P0  = blockIdx.x * TILE;
    const int b   = P0 / NPTS;

    for (int i = tid; i < TILE * 32; i += THREADS) {
        int p = i >> 5, k = i & 31;
        float v = (k < 28) ? x[(size_t)(P0 + p) * 28 + k] : 0.0f;
        __nv_bfloat16 h = __float2bfloat16(v);
        sm[K0_X_H + p * LD_40 + k] = h;
        sm[K0_X_L + p * LD_40 + k] = __float2bfloat16(v - __bfloat162float(h));
    }
    if (tid < TILE) s_cl[tid] = clusters[P0 + tid];

    float acc1[2][2][4];
    init_acc<2, 0>(acc1, b1, nullptr, nullptr);

    gemm2<4, 32, 32, 0, 3, false>(sm, K0_X_H, K0_X_L, LD_40, g_wh + OFF_WIN, g_wl + OFF_WIN,
                                  b_in, nullptr, nullptr, K0_C_H, K0_C_L, LD_136, K0_WS);
    gemm_core<2, 128, 256, 3, false>(acc1, sm, K0_C_H, K0_C_L, LD_136,
                                     g_wh + OFF_W1, g_wl + OFF_W1, K0_WS);
    gemm2<4, 32, 32, 0, 3, false>(sm, K0_X_H, K0_X_L, LD_40,
                                  g_wh + OFF_WIN + 128 * 32, g_wl + OFF_WIN + 128 * 32,
                                  b_in + 128, nullptr, nullptr, K0_C_H, K0_C_L, LD_136, K0_WS);
    gemm_core<2, 128, 256, 3, false>(acc1, sm, K0_C_H, K0_C_L, LD_136,
                                     g_wh + OFF_W1 + 128, g_wl + OFF_W1 + 128, K0_WS);
    epilogue_relu<2>(acc1, sm, K0_M_H, K0_M_L, LD_72);

    gemm2<4, 64, 64, 0, 3, false>(sm, K0_M_H, K0_M_L, LD_72, g_wh + OFF_W2, g_wl + OFF_W2,
                                  b2, nullptr, nullptr, K0_IO_H, K0_IO_L, LD_136, K0_WS);
    __syncthreads();

    store_and_pool(sm, s_cl, 16, b, gfeat, gpool, P0, K0_IO_H, K0_IO_L, LD_136,
                   (float*)(sm + K0_WS));
}

// ---------------- mid: conv3 (P->Q), conv1 (Q+p2l->P), conv2 (P->Q) ----------------
__global__ void __launch_bounds__(THREADS, 2)
mid_kernel(const unsigned* __restrict__ fin, unsigned* __restrict__ fout,
           const int* __restrict__ cl_in, const int* __restrict__ cl_out,
           int nc_in, float* __restrict__ gpool_out, int nc_out,
           const __nv_bfloat16* __restrict__ wh3, const __nv_bfloat16* __restrict__ wl3,
           const float* __restrict__ b3,
           const __nv_bfloat16* __restrict__ wh1, const __nv_bfloat16* __restrict__ wl1,
           const __nv_bfloat16* __restrict__ wh2, const __nv_bfloat16* __restrict__ wl2,
           const float* __restrict__ b2)
{
    extern __shared__ __nv_bfloat16 sm[];
    int* s_cl = (int*)(sm + MF_END);
    const int tid = threadIdx.x;
    const int P0  = blockIdx.x * TILE;
    const int b   = P0 / NPTS;

    for (int i = tid; i < TILE * 128; i += THREADS) {
        int p = i >> 7, c = i & 127;
        unsigned u = fin[(size_t)(P0 + p) * 128 + c];
        sm[MF_P_H + p * LD_136 + c] = __ushort_as_bfloat16((unsigned short)(u & 0xffff));
        sm[MF_P_L + p * LD_136 + c] = __ushort_as_bfloat16((unsigned short)(u >> 16));
    }
    if (tid < TILE) s_cl[tid] = cl_in[P0 + tid];
    else if (tid < 2 * TILE) s_cl[tid] = cl_out[P0 + tid - TILE];

    const float* p2l_b = g_p2l + b * nc_in * 64;

    // conv3 prefetches conv1's chunk0 (COUT 64 <= 128, NCH=4 even)
    gemm2<4, 128, 128, 0, 2, false>(sm, MF_P_H, MF_P_L, LD_136, wh3, wl3, b3,
                                    nullptr, nullptr, MF_Q_H, MF_Q_L, LD_136, MF_WS,
                                    wh1, wl1, 256, 64);
    gemm2<2, 128, 256, 64, 2, true>(sm, MF_Q_H, MF_Q_L, LD_136, wh1, wl1, nullptr,
                                    p2l_b, s_cl, MF_P_H, MF_P_L, LD_72, MF_WS);
    gemm2<4, 64, 64, 0, 2, false>(sm, MF_P_H, MF_P_L, LD_72, wh2, wl2, b2,
                                  nullptr, nullptr, MF_Q_H, MF_Q_L, LD_136, MF_WS);
    __syncthreads();

    store_and_pool(sm, s_cl + TILE, nc_out, b, fout, gpool_out, P0, MF_Q_H, MF_Q_L, LD_136,
                   (float*)sm);
}

// ---------------- final: conv3 (P->Q), out1 (Q+p2l->P), out2 (P->max->out) ----------------
__global__ void __launch_bounds__(THREADS, 2)
final_kernel(const unsigned* __restrict__ fin, const int* __restrict__ cl_in,
             const __nv_bfloat16* __restrict__ wh3, const __nv_bfloat16* __restrict__ wl3,
             const float* __restrict__ b3,
             const float* __restrict__ bo2,
             float* __restrict__ out)
{
    extern __shared__ __nv_bfloat16 sm[];
    int* s_cl = (int*)(sm + MF_END);
    const int tid = threadIdx.x;
    const int P0  = blockIdx.x * TILE;
    const int b   = P0 / NPTS;

    for (int i = tid; i < TILE * 128; i += THREADS) {
        int p = i >> 7, c = i & 127;
        unsigned u = fin[(size_t)(P0 + p) * 128 + c];
        sm[MF_P_H + p * LD_136 + c] = __ushort_as_bfloat16((unsigned short)(u & 0xffff));
        sm[MF_P_L + p * LD_136 + c] = __ushort_as_bfloat16((unsigned short)(u >> 16));
    }
    if (tid < TILE) s_cl[tid] = cl_in[P0 + tid];

    const float* p2l_b = g_p2l + b * 64 * 128;

    // conv3 prefetches out1 chunk0; out1 prefetches out2 chunk0 (all COUT=128, NCH=4)
    gemm2<4, 128, 128, 0, 2, false>(sm, MF_P_H, MF_P_L, LD_136, wh3, wl3, b3,
                                    nullptr, nullptr, MF_Q_H, MF_Q_L, LD_136, MF_WS,
                                    g_wh + OFF_WO1, g_wl + OFF_WO1, 256, 128);
    gemm2<4, 128, 256, 128, 2, true>(sm, MF_Q_H, MF_Q_L, LD_136, g_wh + OFF_WO1, g_wl + OFF_WO1,
                                     nullptr, p2l_b, s_cl, MF_P_H, MF_P_L, LD_136, MF_WS,
                                     g_wh + OFF_WO2, g_wl + OFF_WO2, 128, 128);
    gemm_out<4, 128, 128, true>(sm, MF_P_H, MF_P_L, LD_136, g_wh + OFF_WO2, g_wl + OFF_WO2,
                                bo2, out + b * 128, MF_WS);
}

extern "C" void kernel_launch(void* const* d_in, const int* in_sizes, int n_in,
                              void* d_out, int out_size)
{
    const float* x    = (const float*)d_in[0];
    const int*   cl   = (const int*)  d_in[1];
    const float* w_in = (const float*)d_in[2];
    const float* b_in = (const float*)d_in[3];
    const float* w1   = (const float*)d_in[4];
    const float* b1   = (const float*)d_in[5];
    const float* w2   = (const float*)d_in[6];
    const float* b2   = (const float*)d_in[7];
    const float* w3   = (const float*)d_in[8];
    const float* b3   = (const float*)d_in[9];
    const float* wo1  = (const float*)d_in[10];
    const float* bo1  = (const float*)d_in[11];
    const float* wo2  = (const float*)d_in[12];
    const float* bo2  = (const float*)d_in[13];
    float* out = (float*)d_out;

    void *pa_, *pb_, *pp_, *ph_, *pl_, *pq_;
    cudaGetSymbolAddress(&pa_, g_featA);
    cudaGetSymbolAddress(&pb_, g_featB);
    cudaGetSymbolAddress(&pp_, g_pool);
    cudaGetSymbolAddress(&ph_, g_wh);
    cudaGetSymbolAddress(&pl_, g_wl);
    cudaGetSymbolAddress(&pq_, g_p2l);
    unsigned* fA = (unsigned*)pa_;
    unsigned* fB = (unsigned*)pb_;
    float* pP = (float*)pp_;
    float* pQ = (float*)pq_;
    __nv_bfloat16* wh = (__nv_bfloat16*)ph_;
    __nv_bfloat16* wl = (__nv_bfloat16*)pl_;

    cudaFuncSetAttribute(k0_kernel,    cudaFuncAttributeMaxDynamicSharedMemorySize, SMEM_K0);
    cudaFuncSetAttribute(mid_kernel,   cudaFuncAttributeMaxDynamicSharedMemorySize, SMEM_MF);
    cudaFuncSetAttribute(final_kernel, cudaFuncAttributeMaxDynamicSharedMemorySize, SMEM_MF);

    const int PSTRIDE = BATCH * 64 * 128;

    init_kernel<<<(3 * PSTRIDE + 255) / 256, 256>>>(out);
    convert_all<<<(180224 + 255) / 256, 256>>>(w_in, w1, w2, w3, wo1, wo2);
    warm_kernel<<<1, 32>>>();

    k0_kernel<<<NTILES, THREADS, SMEM_K0>>>(x, cl, b_in, b1, b2, fA, pP);

    p2l_kernel<<<8 * 16, 128>>>(w1 + 1 * 64 * 256, b1 + 64, pP, pQ, 16, 64);
    mid_kernel<<<NTILES, THREADS, SMEM_MF>>>(
        fA, fB, cl, cl + BN, 16, pP + PSTRIDE, 32,
        wh + OFF_W3, wl + OFF_W3, b3,
        wh + OFF_W1 + 64 * 256, wl + OFF_W1 + 64 * 256,
        wh + OFF_W2 + 128 * 64, wl + OFF_W2 + 128 * 64, b2 + 128);

    p2l_kernel<<<8 * 32, 128>>>(w1 + 2 * 64 * 256, b1 + 128, pP + PSTRIDE, pQ, 32, 64);
    mid_kernel<<<NTILES, THREADS, SMEM_MF>>>(
        fB, fA, cl + BN, cl + 2 * BN, 32, pP + 2 * PSTRIDE, 64,
        wh + OFF_W3 + 128 * 128, wl + OFF_W3 + 128 * 128, b3 + 128,
        wh + OFF_W1 + 2 * 64 * 256, wl + OFF_W1 + 2 * 64 * 256,
        wh + OFF_W2 + 2 * 128 * 64, wl + OFF_W2 + 2 * 128 * 64, b2 + 2 * 128);

    p2l_kernel<<<8 * 64, 128>>>(wo1, bo1, pP + 2 * PSTRIDE, pQ, 64, 128);
    final_kernel<<<NTILES, THREADS, SMEM_MF>>>(
        fA, cl + 2 * BN,
        wh + OFF_W3 + 2 * 128 * 128, wl + OFF_W3 + 2 * 128 * 128, b3 + 2 * 128,
        bo2, out);
}

// round 17
// speedup vs baseline: 1.6384x; 1.2804x over previous
#include <cuda_runtime.h>
#include <cuda_fp16.h>

#define BATCH   8
#define NPTS    16384
#define BN      (BATCH * NPTS)
#define TILE    64
#define NTILES  (BN / TILE)        // 2048
#define THREADS 256                // 8 warps: 2 m-groups(32 rows) x 4 n-groups

// ---------------- mid/final smem layout (fp16 elements) ----------------
#define MF_P    0                  // 64x136 (input feats; conv1 out overlays)
#define MF_Q    8704               // 64x136
#define MF_WS   17408              // weight ring: 2 bufs x (128x32 x 2 planes) = 16384
#define MF_END  33792
#define SMEM_MF (MF_END*2 + 512)   // 68096 B -> 2 CTAs/SM

// ---------------- k0 smem layout ----------------
#define K0_X    0                  // 64x40
#define K0_C    2560               // 64x136 (half of mlp_in output; reused)
#define K0_M    11264              // 64x72 (conv1 out)
#define K0_IO   2560               // conv2 out overlays C
#define K0_WS   15872              // 16384-elem ring
#define K0_END  32256
#define SMEM_K0 (K0_END*2 + 512)   // 65024 B -> 2 CTAs/SM

#define LD_136 136
#define LD_72  72
#define LD_40  40

// ---------------- global scratch ----------------
__device__ unsigned g_featA[BN * 64];      // fp16 features packed 2/word
__device__ unsigned g_featB[BN * 64];
__device__ float    g_pool[3 * BATCH * 64 * 128];
__device__ float    g_p2l[8 * 64 * 128];
__device__ __half   g_wh[180224];
__device__ __half   g_wl[180224];

#define OFF_WIN 0        // 256 x 32
#define OFF_W1  8192     // 3 x (64 x 256)
#define OFF_W2  57344    // 3 x (128 x 64)
#define OFF_W3  81920    // 3 x (128 x 128)
#define OFF_WO1 131072   // 128 x 256
#define OFF_WO2 163840   // 128 x 128

__global__ void init_kernel(float* __restrict__ out) {
    int i = blockIdx.x * blockDim.x + threadIdx.x;
    if (i < 3 * BATCH * 64 * 128) g_pool[i] = 0.0f;
    if (i < BATCH * 128) out[i] = 0.0f;
}

__global__ void warm_kernel() {}

__global__ void convert_all(const float* __restrict__ w_in, const float* __restrict__ w1,
                            const float* __restrict__ w2, const float* __restrict__ w3,
                            const float* __restrict__ wo1, const float* __restrict__ wo2) {
    int i = blockIdx.x * blockDim.x + threadIdx.x;
    if (i >= 180224) return;
    const float* src; int base, cin, kpad;
    if (i < 8192)        { src = w_in; base = 0;      cin = 28;  kpad = 32;  }
    else if (i < 57344)  { src = w1;   base = 8192;   cin = 256; kpad = 256; }
    else if (i < 81920)  { src = w2;   base = 57344;  cin = 64;  kpad = 64;  }
    else if (i < 131072) { src = w3;   base = 81920;  cin = 128; kpad = 128; }
    else if (i < 163840) { src = wo1;  base = 131072; cin = 256; kpad = 256; }
    else                 { src = wo2;  base = 163840; cin = 128; kpad = 128; }
    int j = i - base, r = j / kpad, k = j - r * kpad;
    float v = (k < cin) ? src[r * cin + k] : 0.0f;
    __half h = __float2half(v);
    g_wh[i] = h;
    g_wl[i] = __float2half(v - __half2float(h));
}

// p2l[b][cl][j] = bias[j] + W[j][128..255] . pool[b][cl][:]
__global__ void p2l_kernel(const float* __restrict__ w, const float* __restrict__ bias,
                           const float* __restrict__ pool, float* __restrict__ dst,
                           int ncl, int J) {
    __shared__ float sp[128];
    int bc = blockIdx.x;
    int b = bc / ncl, cl = bc - b * ncl;
    sp[threadIdx.x] = pool[b * 8192 + cl * 128 + threadIdx.x];
    __syncthreads();
    for (int j = threadIdx.x; j < J; j += 128) {
        const float4* wr = (const float4*)(w + j * 256 + 128);
        float s = bias[j];
#pragma unroll
        for (int k = 0; k < 32; k++) {
            float4 wv = wr[k];
            float4 pv = ((const float4*)sp)[k];
            s += wv.x * pv.x + wv.y * pv.y + wv.z * pv.z + wv.w * pv.w;
        }
        dst[bc * J + j] = s;
    }
}

// ---------------- helpers ----------------
__device__ __forceinline__ void mma_f16(float c[4], const unsigned a[4],
                                        unsigned b0, unsigned b1) {
    asm volatile(
        "mma.sync.aligned.m16n8k16.row.col.f32.f16.f16.f32 "
        "{%0,%1,%2,%3}, {%4,%5,%6,%7}, {%8,%9}, {%0,%1,%2,%3};"
        : "+f"(c[0]), "+f"(c[1]), "+f"(c[2]), "+f"(c[3])
        : "r"(a[0]), "r"(a[1]), "r"(a[2]), "r"(a[3]), "r"(b0), "r"(b1));
}
__device__ __forceinline__ unsigned sptr(const void* p) {
    return (unsigned)__cvta_generic_to_shared(p);
}
__device__ __forceinline__ void ldsm4(unsigned r[4], const void* p) {
    asm volatile("ldmatrix.sync.aligned.m8n8.x4.shared.b16 {%0,%1,%2,%3}, [%4];"
                 : "=r"(r[0]), "=r"(r[1]), "=r"(r[2]), "=r"(r[3]) : "r"(sptr(p)));
}
__device__ __forceinline__ unsigned pack2(__half x, __half y) {
    return ((unsigned)__half_as_ushort(y) << 16) | (unsigned)__half_as_ushort(x);
}
#define CP16(d, s) asm volatile("cp.async.cg.shared.global [%0], [%1], 16;" :: "r"(d), "l"(s))

// stage one KC=32 chunk of split-fp16 weights [cout x 32] (hi+lo planes), 64B rows,
// XOR swizzle seg^=(row>>1)&3 (conflict-free ldmatrix + cp.async)
__device__ __forceinline__ void stage_chunk(__half* base,
        const __half* __restrict__ wh, const __half* __restrict__ wl,
        int wstr, int cout, int kcol)
{
    const int tid = threadIdx.x;
    const int pl_elems = cout * 32;
    for (int idx = tid; idx < 2 * cout * 4; idx += THREADS) {
        int pl = idx >= cout * 4;
        int j  = idx - pl * cout * 4;
        int row = j >> 2, s = j & 3;
        const __half* src = (pl ? wl : wh) + row * wstr + kcol + s * 8;
        CP16(sptr(base + pl * pl_elems + row * 32 + ((s ^ ((row >> 1) & 3)) << 3)), src);
    }
    asm volatile("cp.async.commit_group;");
}

// ================= GEMM mainloop: KC=32 double-buffered, fp16 2-term =================
// acc += A * (Wh + Wl); A single fp16 plane, weights split-fp16 (exact).
// 8 warps: 2 m-groups(32 rows) x 4 n-groups. acc[2][NT][4].
template<int NT, int KW, int WSTR>
__device__ __forceinline__ void gemm_core(float (*acc)[NT][4], __half* sm,
                                          int aOff, int ldA,
                                          const __half* __restrict__ gWh,
                                          const __half* __restrict__ gWl,
                                          int wsOff)
{
    constexpr int COUT = NT * 32;
    constexpr int NCH  = KW / 32;
    constexpr int PL   = COUT * 32;
    constexpr int BUF  = 2 * PL;
    const int tid  = threadIdx.x;
    const int lane = tid & 31;
    const int w    = tid >> 5;
    const int mg   = w & 1;
    const int ng   = w >> 1;

    const int arow = mg * 32 + (lane & 15);
    const int ac8  = ((lane >> 4) & 1) * 8;
    const __half* pA0 = sm + aOff + arow * ldA + ac8;
    const int brow = (lane & 7) + ((lane >> 4) & 1) * 8;
    const int bseg = (lane >> 3) & 1;

    __syncthreads();   // prior users of ring done / prior-stage activations visible
    stage_chunk(sm + wsOff, gWh, gWl, WSTR, COUT, 0);
    if (NCH > 1) stage_chunk(sm + wsOff + BUF, gWh, gWl, WSTR, COUT, 32);

#pragma unroll
    for (int ch = 0; ch < NCH; ch++) {
        if (ch < NCH - 1) asm volatile("cp.async.wait_group 1;" ::: "memory");
        else              asm volatile("cp.async.wait_group 0;" ::: "memory");
        __syncthreads();   // chunk ch visible CTA-wide
        const __half* wb = sm + wsOff + (ch & 1) * BUF;
#pragma unroll
        for (int ks = 0; ks < 32; ks += 16) {
            unsigned ah[2][4];
            ldsm4(ah[0], pA0 + ch * 32 + ks);
            ldsm4(ah[1], pA0 + 16 * ldA + ch * 32 + ks);
            const int s0 = (ks >> 3) | bseg;
#pragma unroll
            for (int nt = 0; nt < NT; nt += 2) {
                unsigned bh[4], bl[4];
                int r0 = ng * (NT * 8) + nt * 8 + brow;
                int o0 = r0 * 32 + ((s0 ^ ((r0 >> 1) & 3)) << 3);
                ldsm4(bh, wb + o0);
                ldsm4(bl, wb + PL + o0);
#pragma unroll
                for (int mt = 0; mt < 2; mt++) {
                    mma_f16(acc[mt][nt],     ah[mt], bh[0], bh[1]);
                    mma_f16(acc[mt][nt],     ah[mt], bl[0], bl[1]);
                    mma_f16(acc[mt][nt + 1], ah[mt], bh[2], bh[3]);
                    mma_f16(acc[mt][nt + 1], ah[mt], bl[2], bl[3]);
                }
            }
        }
        if (ch + 2 < NCH) {
            __syncthreads();
            stage_chunk(sm + wsOff + ((ch + 2) & 1) * BUF, gWh, gWl, WSTR, COUT, (ch + 2) * 32);
        }
    }
}

// relu + fp16 smem writeback (single plane)
template<int NT>
__device__ __forceinline__ void epilogue_relu(float (*acc)[NT][4], __half* sm,
                                              int cOff, int ldC)
{
    const int tid  = threadIdx.x;
    const int lane = tid & 31;
    const int w    = tid >> 5;
    const int g    = lane >> 2;
    const int t    = lane & 3;
    const int mg   = w & 1;
    const int ng   = w >> 1;
    __half* sC = sm + cOff;
#pragma unroll
    for (int mt = 0; mt < 2; mt++) {
#pragma unroll
        for (int nt = 0; nt < NT; nt++) {
            int n0 = ng * (NT * 8) + nt * 8 + 2 * t;
            int r = mg * 32 + mt * 16 + g;
            float v0 = fmaxf(acc[mt][nt][0], 0.0f);
            float v1 = fmaxf(acc[mt][nt][1], 0.0f);
            float v2 = fmaxf(acc[mt][nt][2], 0.0f);
            float v3 = fmaxf(acc[mt][nt][3], 0.0f);
            *(unsigned*)(sC + r * ldC + n0)       = pack2(__float2half(v0), __float2half(v1));
            *(unsigned*)(sC + (r + 8) * ldC + n0) = pack2(__float2half(v2), __float2half(v3));
        }
    }
}

// acc init: bias (+ optional per-cluster p2l gather)
template<int NT, int JSTR>
__device__ __forceinline__ void init_acc(float (*acc)[NT][4], const float* gBias,
                                         const float* p2l, const int* s_cl)
{
    const int tid  = threadIdx.x;
    const int lane = tid & 31;
    const int w    = tid >> 5;
    const int g    = lane >> 2;
    const int t    = lane & 3;
    const int mg   = w & 1;
    const int ng   = w >> 1;
#pragma unroll
    for (int mt = 0; mt < 2; mt++) {
#pragma unroll
        for (int nt = 0; nt < NT; nt++) {
            int n0 = ng * (NT * 8) + nt * 8 + 2 * t;
            float b0 = gBias ? gBias[n0] : 0.0f;
            float b1 = gBias ? gBias[n0 + 1] : 0.0f;
            if (JSTR) {
                int c0 = s_cl[mg * 32 + mt * 16 + g];
                int c1 = s_cl[mg * 32 + mt * 16 + g + 8];
                acc[mt][nt][0] = b0 + p2l[c0 * JSTR + n0];
                acc[mt][nt][1] = b1 + p2l[c0 * JSTR + n0 + 1];
                acc[mt][nt][2] = b0 + p2l[c1 * JSTR + n0];
                acc[mt][nt][3] = b1 + p2l[c1 * JSTR + n0 + 1];
            } else {
                acc[mt][nt][0] = b0; acc[mt][nt][1] = b1;
                acc[mt][nt][2] = b0; acc[mt][nt][3] = b1;
            }
        }
    }
}

template<int NT, int KW, int WSTR, int JSTR>
__device__ void gemm2(__half* sm, int aOff, int ldA,
                      const __half* __restrict__ gWh,
                      const __half* __restrict__ gWl,
                      const float* __restrict__ gBias,
                      const float* __restrict__ p2l, const int* __restrict__ s_cl,
                      int cOff, int ldC, int wsOff)
{
    float acc[2][NT][4];
    init_acc<NT, JSTR>(acc, gBias, p2l, s_cl);
    gemm_core<NT, KW, WSTR>(acc, sm, aOff, ldA, gWh, gWl, wsOff);
    epilogue_relu<NT>(acc, sm, cOff, ldC);
}

// final GEMM: relu -> per-column tile max -> global atomicMax
template<int NT, int KW, int WSTR>
__device__ void gemm_out(__half* sm, int aOff, int ldA,
                         const __half* __restrict__ gWh,
                         const __half* __restrict__ gWl,
                         const float* __restrict__ gBias,
                         float* __restrict__ outb, int wsOff)
{
    const int lane = threadIdx.x & 31;
    const int t    = lane & 3;
    const int ng   = (threadIdx.x >> 5) >> 1;

    float acc[2][NT][4];
    init_acc<NT, 0>(acc, gBias, nullptr, nullptr);
    gemm_core<NT, KW, WSTR>(acc, sm, aOff, ldA, gWh, gWl, wsOff);

#pragma unroll
    for (int nt = 0; nt < NT; nt++) {
        int n0 = ng * (NT * 8) + nt * 8 + 2 * t;
        float m0 = 0.0f, m1 = 0.0f;
#pragma unroll
        for (int mt = 0; mt < 2; mt++) {
            m0 = fmaxf(m0, fmaxf(acc[mt][nt][0], acc[mt][nt][2]));
            m1 = fmaxf(m1, fmaxf(acc[mt][nt][1], acc[mt][nt][3]));
        }
#pragma unroll
        for (int o = 4; o < 32; o <<= 1) {
            m0 = fmaxf(m0, __shfl_xor_sync(0xffffffff, m0, o));
            m1 = fmaxf(m1, __shfl_xor_sync(0xffffffff, m1, o));
        }
        if ((lane >> 2) == 0) {
            atomicMax((int*)&outb[n0],     __float_as_int(m0));
            atomicMax((int*)&outb[n0 + 1], __float_as_int(m1));
        }
    }
}

// ---------------- feature store + segment-max pool ----------------
__device__ void store_and_pool(__half* sm, const int* s_cl, int nc, int b,
                               unsigned* __restrict__ gfeat, float* __restrict__ gpool,
                               int P0, int qOff, int ldQ, float* spool)
{
    const int tid = threadIdx.x;
    for (int i = tid; i < TILE * 64; i += THREADS) {
        int p = i >> 6, c2 = i & 63;
        gfeat[(size_t)(P0 + p) * 64 + c2] = *(unsigned*)(sm + qOff + p * ldQ + 2 * c2);
    }
    for (int i = tid; i < nc * 128; i += THREADS) spool[i] = 0.0f;
    __syncthreads();
    for (int i = tid; i < TILE * 128; i += THREADS) {
        int p = i >> 7, c = i & 127;
        float v = __half2float(sm[qOff + p * ldQ + c]);
        atomicMax((int*)&spool[s_cl[p] * 128 + c], __float_as_int(v));
    }
    __syncthreads();
    for (int i = tid; i < nc * 128; i += THREADS) {
        float v = spool[i];
        if (v > 0.0f)
            atomicMax((int*)&gpool[b * (64 * 128) + i], __float_as_int(v));
    }
}

// ---------------- K0: split-K ----------------
__global__ void __launch_bounds__(THREADS, 2)
k0_kernel(const float* __restrict__ x, const int* __restrict__ clusters,
          const float* __restrict__ b_in, const float* __restrict__ b1,
          const float* __restrict__ b2,
          unsigned* __restrict__ gfeat, float* __restrict__ gpool)
{
    extern __shared__ __half sm[];
    int* s_cl = (int*)(sm + K0_END);
    const int tid = threadIdx.x;
    const int P0  = blockIdx.x * TILE;
    const int b   = P0 / NPTS;

    for (int i = tid; i < TILE * 32; i += THREADS) {
        int p = i >> 5, k = i & 31;
        float v = (k < 28) ? x[(size_t)(P0 + p) * 28 + k] : 0.0f;
        sm[K0_X + p * LD_40 + k] = __float2half(v);
    }
    if (tid < TILE) s_cl[tid] = clusters[P0 + tid];

    float acc1[2][2][4];
    init_acc<2, 0>(acc1, b1, nullptr, nullptr);

    gemm2<4, 32, 32, 0>(sm, K0_X, LD_40, g_wh + OFF_WIN, g_wl + OFF_WIN,
                        b_in, nullptr, nullptr, K0_C, LD_136, K0_WS);
    gemm_core<2, 128, 256>(acc1, sm, K0_C, LD_136,
                           g_wh + OFF_W1, g_wl + OFF_W1, K0_WS);
    gemm2<4, 32, 32, 0>(sm, K0_X, LD_40,
                        g_wh + OFF_WIN + 128 * 32, g_wl + OFF_WIN + 128 * 32,
                        b_in + 128, nullptr, nullptr, K0_C, LD_136, K0_WS);
    gemm_core<2, 128, 256>(acc1, sm, K0_C, LD_136,
                           g_wh + OFF_W1 + 128, g_wl + OFF_W1 + 128, K0_WS);
    epilogue_relu<2>(acc1, sm, K0_M, LD_72);

    gemm2<4, 64, 64, 0>(sm, K0_M, LD_72, g_wh + OFF_W2, g_wl + OFF_W2,
                        b2, nullptr, nullptr, K0_IO, LD_136, K0_WS);
    __syncthreads();

    store_and_pool(sm, s_cl, 16, b, gfeat, gpool, P0, K0_IO, LD_136,
                   (float*)(sm + K0_WS));
}

// ---------------- mid: conv3 (P->Q), conv1 (Q+p2l->P), conv2 (P->Q) ----------------
__global__ void __launch_bounds__(THREADS, 2)
mid_kernel(const unsigned* __restrict__ fin, unsigned* __restrict__ fout,
           const int* __restrict__ cl_in, const int* __restrict__ cl_out,
           int nc_in, float* __restrict__ gpool_out, int nc_out,
           const __half* __restrict__ wh3, const __half* __restrict__ wl3,
           const float* __restrict__ b3,
           const __half* __restrict__ wh1, const __half* __restrict__ wl1,
           const __half* __restrict__ wh2, const __half* __restrict__ wl2,
           const float* __restrict__ b2)
{
    extern __shared__ __half sm[];
    int* s_cl = (int*)(sm + MF_END);
    const int tid = threadIdx.x;
    const int P0  = blockIdx.x * TILE;
    const int b   = P0 / NPTS;

    for (int i = tid; i < TILE * 64; i += THREADS) {
        int p = i >> 6, c2 = i & 63;
        *(unsigned*)(sm + MF_P + p * LD_136 + 2 * c2) = fin[(size_t)(P0 + p) * 64 + c2];
    }
    if (tid < TILE) s_cl[tid] = cl_in[P0 + tid];
    else if (tid < 2 * TILE) s_cl[tid] = cl_out[P0 + tid - TILE];

    const float* p2l_b = g_p2l + b * nc_in * 64;

    gemm2<4, 128, 128, 0>(sm, MF_P, LD_136, wh3, wl3, b3,
                          nullptr, nullptr, MF_Q, LD_136, MF_WS);
    gemm2<2, 128, 256, 64>(sm, MF_Q, LD_136, wh1, wl1, nullptr,
                           p2l_b, s_cl, MF_P, LD_72, MF_WS);
    gemm2<4, 64, 64, 0>(sm, MF_P, LD_72, wh2, wl2, b2,
                        nullptr, nullptr, MF_Q, LD_136, MF_WS);
    __syncthreads();

    store_and_pool(sm, s_cl + TILE, nc_out, b, fout, gpool_out, P0, MF_Q, LD_136,
                   (float*)(sm + MF_WS));
}

// ---------------- final: conv3 (P->Q), out1 (Q+p2l->P), out2 (P->max->out) ----------------
__global__ void __launch_bounds__(THREADS, 2)
final_kernel(const unsigned* __restrict__ fin, const int* __restrict__ cl_in,
             const __half* __restrict__ wh3, const __half* __restrict__ wl3,
             const float* __restrict__ b3,
             const float* __restrict__ bo2,
             float* __restrict__ out)
{
    extern __shared__ __half sm[];
    int* s_cl = (int*)(sm + MF_END);
    const int tid = threadIdx.x;
    const int P0  = blockIdx.x * TILE;
    const int b   = P0 / NPTS;

    for (int i = tid; i < TILE * 64; i += THREADS) {
        int p = i >> 6, c2 = i & 63;
        *(unsigned*)(sm + MF_P + p * LD_136 + 2 * c2) = fin[(size_t)(P0 + p) * 64 + c2];
    }
    if (tid < TILE) s_cl[tid] = cl_in[P0 + tid];

    const float* p2l_b = g_p2l + b * 64 * 128;

    gemm2<4, 128, 128, 0>(sm, MF_P, LD_136, wh3, wl3, b3,
                          nullptr, nullptr, MF_Q, LD_136, MF_WS);
    gemm2<4, 128, 256, 128>(sm, MF_Q, LD_136, g_wh + OFF_WO1, g_wl + OFF_WO1,
                            nullptr, p2l_b, s_cl, MF_P, LD_136, MF_WS);
    gemm_out<4, 128, 128>(sm, MF_P, LD_136, g_wh + OFF_WO2, g_wl + OFF_WO2,
                          bo2, out + b * 128, MF_WS);
}

extern "C" void kernel_launch(void* const* d_in, const int* in_sizes, int n_in,
                              void* d_out, int out_size)
{
    const float* x    = (const float*)d_in[0];
    const int*   cl   = (const int*)  d_in[1];
    const float* w_in = (const float*)d_in[2];
    const float* b_in = (const float*)d_in[3];
    const float* w1   = (const float*)d_in[4];
    const float* b1   = (const float*)d_in[5];
    const float* w2   = (const float*)d_in[6];
    const float* b2   = (const float*)d_in[7];
    const float* w3   = (const float*)d_in[8];
    const float* b3   = (const float*)d_in[9];
    const float* wo1  = (const float*)d_in[10];
    const float* bo1  = (const float*)d_in[11];
    const float* wo2  = (const float*)d_in[12];
    const float* bo2  = (const float*)d_in[13];
    float* out = (float*)d_out;

    void *pa_, *pb_, *pp_, *ph_, *pl_, *pq_;
    cudaGetSymbolAddress(&pa_, g_featA);
    cudaGetSymbolAddress(&pb_, g_featB);
    cudaGetSymbolAddress(&pp_, g_pool);
    cudaGetSymbolAddress(&ph_, g_wh);
    cudaGetSymbolAddress(&pl_, g_wl);
    cudaGetSymbolAddress(&pq_, g_p2l);
    unsigned* fA = (unsigned*)pa_;
    unsigned* fB = (unsigned*)pb_;
    float* pP = (float*)pp_;
    float* pQ = (float*)pq_;
    __half* wh = (__half*)ph_;
    __half* wl = (__half*)pl_;

    cudaFuncSetAttribute(k0_kernel,    cudaFuncAttributeMaxDynamicSharedMemorySize, SMEM_K0);
    cudaFuncSetAttribute(mid_kernel,   cudaFuncAttributeMaxDynamicSharedMemorySize, SMEM_MF);
    cudaFuncSetAttribute(final_kernel, cudaFuncAttributeMaxDynamicSharedMemorySize, SMEM_MF);

    const int PSTRIDE = BATCH * 64 * 128;

    init_kernel<<<(3 * PSTRIDE + 255) / 256, 256>>>(out);
    convert_all<<<(180224 + 255) / 256, 256>>>(w_in, w1, w2, w3, wo1, wo2);
    warm_kernel<<<1, 32>>>();

    k0_kernel<<<NTILES, THREADS, SMEM_K0>>>(x, cl, b_in, b1, b2, fA, pP);

    p2l_kernel<<<8 * 16, 128>>>(w1 + 1 * 64 * 256, b1 + 64, pP, pQ, 16, 64);
    mid_kernel<<<NTILES, THREADS, SMEM_MF>>>(
        fA, fB, cl, cl + BN, 16, pP + PSTRIDE, 32,
        wh + OFF_W3, wl + OFF_W3, b3,
        wh + OFF_W1 + 64 * 256, wl + OFF_W1 + 64 * 256,
        wh + OFF_W2 + 128 * 64, wl + OFF_W2 + 128 * 64, b2 + 128);

    p2l_kernel<<<8 * 32, 128>>>(w1 + 2 * 64 * 256, b1 + 128, pP + PSTRIDE, pQ, 32, 64);
    mid_kernel<<<NTILES, THREADS, SMEM_MF>>>(
        fB, fA, cl + BN, cl + 2 * BN, 32, pP + 2 * PSTRIDE, 64,
        wh + OFF_W3 + 128 * 128, wl + OFF_W3 + 128 * 128, b3 + 128,
        wh + OFF_W1 + 2 * 64 * 256, wl + OFF_W1 + 2 * 64 * 256,
        wh + OFF_W2 + 2 * 128 * 64, wl + OFF_W2 + 2 * 128 * 64, b2 + 2 * 128);

    p2l_kernel<<<8 * 64, 128>>>(wo1, bo1, pP + 2 * PSTRIDE, pQ, 64, 128);
    final_kernel<<<NTILES, THREADS, SMEM_MF>>>(
        fA, cl + 2 * BN,
        wh + OFF_W3 + 2 * 128 * 128, wl + OFF_W3 + 2 * 128 * 128, b3 + 2 * 128,
        bo2, out);
}